// round 1
// baseline (speedup 1.0000x reference)
#include <cuda_runtime.h>

#define BATCH 2
#define SEQ   2048
#define NHEAD 16
#define HDIM  64
#define DM    1024            // NHEAD*HDIM
#define MTOT  (BATCH*SEQ)     // 4096

#define ROWS 128              // query rows per attention block
#define TK   64               // key tile

// Scratch for Q/K/V projections (no cudaMalloc allowed).
__device__ float g_q[MTOT * DM];
__device__ float g_k[MTOT * DM];
__device__ float g_v[MTOT * DM];

// ---------------------------------------------------------------------------
// QKV projection GEMM: out = x[M,K] @ W[K,N] + bias
// 64x64 block tile, 16 k-tile, 256 threads, 4x4 per-thread micro-tile.
// blockIdx.z selects which of {wq,wk,wv} / {g_q,g_k,g_v}.
// ---------------------------------------------------------------------------
__global__ __launch_bounds__(256) void qkv_gemm(
    const float* __restrict__ x,
    const float* __restrict__ wq, const float* __restrict__ bq,
    const float* __restrict__ wk, const float* __restrict__ bk,
    const float* __restrict__ wv, const float* __restrict__ bv)
{
    const float* W; const float* bias; float* out;
    if (blockIdx.z == 0)      { W = wq; bias = bq; out = g_q; }
    else if (blockIdx.z == 1) { W = wk; bias = bk; out = g_k; }
    else                      { W = wv; bias = bv; out = g_v; }

    __shared__ __align__(16) float As[16][68];  // [k][m], padded vs stride-64 conflicts
    __shared__ __align__(16) float Bs[16][64];  // [k][n]

    const int tid = threadIdx.x;
    const int tx = tid & 15, ty = tid >> 4;
    const int row0 = blockIdx.y * 64;
    const int col0 = blockIdx.x * 64;

    // A-tile load mapping: one float4 per thread per k-tile
    const int arow = tid >> 2;        // 0..63
    const int acol = (tid & 3) * 4;   // 0,4,8,12
    // B-tile load mapping
    const int brow = tid >> 4;        // 0..15
    const int bcol = (tid & 15) * 4;  // 0..60

    float acc[4][4] = {};

    for (int k0 = 0; k0 < DM; k0 += 16) {
        float4 a = *(const float4*)&x[(row0 + arow) * DM + k0 + acol];
        As[acol + 0][arow] = a.x;
        As[acol + 1][arow] = a.y;
        As[acol + 2][arow] = a.z;
        As[acol + 3][arow] = a.w;
        *(float4*)&Bs[brow][bcol] =
            *(const float4*)&W[(k0 + brow) * DM + col0 + bcol];
        __syncthreads();

        #pragma unroll
        for (int k = 0; k < 16; k++) {
            float4 av = *(float4*)&As[k][ty * 4];
            float4 bv4 = *(float4*)&Bs[k][tx * 4];
            float ar[4] = {av.x, av.y, av.z, av.w};
            float br[4] = {bv4.x, bv4.y, bv4.z, bv4.w};
            #pragma unroll
            for (int i = 0; i < 4; i++)
                #pragma unroll
                for (int j = 0; j < 4; j++)
                    acc[i][j] = fmaf(ar[i], br[j], acc[i][j]);
        }
        __syncthreads();
    }

    #pragma unroll
    for (int i = 0; i < 4; i++) {
        const int r = row0 + ty * 4 + i;
        const int c = col0 + tx * 4;
        float4 o;
        o.x = acc[i][0] + bias[c + 0];
        o.y = acc[i][1] + bias[c + 1];
        o.z = acc[i][2] + bias[c + 2];
        o.w = acc[i][3] + bias[c + 3];
        *(float4*)&out[r * DM + c] = o;
    }
}

// ---------------------------------------------------------------------------
// Attention: one thread per query row, flash-style online softmax.
// grid = (SEQ/ROWS, NHEAD, BATCH), block = ROWS threads.
// ---------------------------------------------------------------------------
__global__ __launch_bounds__(ROWS) void attn_kernel(float* __restrict__ out)
{
    const int b = blockIdx.z;
    const int h = blockIdx.y;
    const int q0 = blockIdx.x * ROWS;
    const int tid = threadIdx.x;

    __shared__ __align__(16) float Ks[TK][HDIM];
    __shared__ __align__(16) float Vs[TK][HDIM];

    const float scale = 0.125f;  // 1/sqrt(64)
    const int qrow = b * SEQ + q0 + tid;

    // Pre-scaled Q row in registers
    float q[HDIM];
    {
        const float4* qp = (const float4*)&g_q[(size_t)qrow * DM + h * HDIM];
        #pragma unroll
        for (int i = 0; i < HDIM / 4; i++) {
            float4 v = qp[i];
            q[4*i+0] = v.x * scale;
            q[4*i+1] = v.y * scale;
            q[4*i+2] = v.z * scale;
            q[4*i+3] = v.w * scale;
        }
    }

    float m = -1e30f, l = 0.f;
    float o[HDIM] = {};

    for (int kb = 0; kb < SEQ; kb += TK) {
        __syncthreads();
        // Load K/V tiles (64 rows x 64 dims), 8 float4 per thread per tile
        #pragma unroll
        for (int i = 0; i < 8; i++) {
            int idx = i * ROWS + tid;        // 0..1023
            int kr = idx >> 4;               // 0..63
            int dg = (idx & 15) * 4;         // 0..60
            size_t goff = (size_t)(b * SEQ + kb + kr) * DM + h * HDIM + dg;
            *(float4*)&Ks[kr][dg] = *(const float4*)&g_k[goff];
            *(float4*)&Vs[kr][dg] = *(const float4*)&g_v[goff];
        }
        __syncthreads();

        for (int j = 0; j < TK; j++) {
            // s = q . K[j]   (4 independent accumulator chains for ILP)
            float s0 = 0.f, s1 = 0.f, s2 = 0.f, s3 = 0.f;
            #pragma unroll
            for (int d = 0; d < HDIM; d += 4) {
                float4 kv = *(float4*)&Ks[j][d];
                s0 = fmaf(q[d + 0], kv.x, s0);
                s1 = fmaf(q[d + 1], kv.y, s1);
                s2 = fmaf(q[d + 2], kv.z, s2);
                s3 = fmaf(q[d + 3], kv.w, s3);
            }
            float s = (s0 + s1) + (s2 + s3);

            if (s > m) {                      // rare: ~ln(SEQ) times per row
                float alpha = __expf(m - s);
                l *= alpha;
                #pragma unroll
                for (int d = 0; d < HDIM; d++) o[d] *= alpha;
                m = s;
            }
            float p = __expf(s - m);
            l += p;
            #pragma unroll
            for (int d = 0; d < HDIM; d += 4) {
                float4 vv = *(float4*)&Vs[j][d];
                o[d + 0] = fmaf(p, vv.x, o[d + 0]);
                o[d + 1] = fmaf(p, vv.y, o[d + 1]);
                o[d + 2] = fmaf(p, vv.z, o[d + 2]);
                o[d + 3] = fmaf(p, vv.w, o[d + 3]);
            }
        }
    }

    const float inv_l = 1.f / l;
    float* op = &out[(size_t)qrow * DM + h * HDIM];
    #pragma unroll
    for (int d = 0; d < HDIM; d += 4) {
        float4 v;
        v.x = o[d + 0] * inv_l;
        v.y = o[d + 1] * inv_l;
        v.z = o[d + 2] * inv_l;
        v.w = o[d + 3] * inv_l;
        *(float4*)&op[d] = v;
    }
}

// ---------------------------------------------------------------------------
extern "C" void kernel_launch(void* const* d_in, const int* in_sizes, int n_in,
                              void* d_out, int out_size)
{
    const float* x  = (const float*)d_in[0];
    const float* wq = (const float*)d_in[1];
    const float* bq = (const float*)d_in[2];
    const float* wk = (const float*)d_in[3];
    const float* bk = (const float*)d_in[4];
    const float* wv = (const float*)d_in[5];
    const float* bv = (const float*)d_in[6];
    float* out = (float*)d_out;

    dim3 gGemm(DM / 64, MTOT / 64, 3);
    qkv_gemm<<<gGemm, 256>>>(x, wq, bq, wk, bk, wv, bv);

    dim3 gAttn(SEQ / ROWS, NHEAD, BATCH);
    attn_kernel<<<gAttn, ROWS>>>(out);
}

// round 2
// speedup vs baseline: 1.0011x; 1.0011x over previous
#include <cuda_runtime.h>

#define BATCH 2
#define SEQ   2048
#define NHEAD 16
#define HDIM  64
#define DM    1024            // NHEAD*HDIM
#define MTOT  (BATCH*SEQ)     // 4096

#define ROWS 128              // query rows per attention block
#define TK   64               // key tile

// Scratch for Q/K/V projections (no cudaMalloc allowed).
__device__ float g_q[MTOT * DM];
__device__ float g_k[MTOT * DM];
__device__ float g_v[MTOT * DM];

// ---------------------------------------------------------------------------
// QKV projection GEMM: out = x[M,K] @ W[K,N] + bias
// 64x64 block tile, 16 k-tile, 256 threads, 4x4 per-thread micro-tile.
// blockIdx.z selects which of {wq,wk,wv} / {g_q,g_k,g_v}.
// ---------------------------------------------------------------------------
__global__ __launch_bounds__(256) void qkv_gemm(
    const float* __restrict__ x,
    const float* __restrict__ wq, const float* __restrict__ bq,
    const float* __restrict__ wk, const float* __restrict__ bk,
    const float* __restrict__ wv, const float* __restrict__ bv)
{
    const float* W; const float* bias; float* out;
    if (blockIdx.z == 0)      { W = wq; bias = bq; out = g_q; }
    else if (blockIdx.z == 1) { W = wk; bias = bk; out = g_k; }
    else                      { W = wv; bias = bv; out = g_v; }

    __shared__ __align__(16) float As[16][68];  // [k][m], padded vs stride-64 conflicts
    __shared__ __align__(16) float Bs[16][64];  // [k][n]

    const int tid = threadIdx.x;
    const int tx = tid & 15, ty = tid >> 4;
    const int row0 = blockIdx.y * 64;
    const int col0 = blockIdx.x * 64;

    // A-tile load mapping: one float4 per thread per k-tile
    const int arow = tid >> 2;        // 0..63
    const int acol = (tid & 3) * 4;   // 0,4,8,12
    // B-tile load mapping
    const int brow = tid >> 4;        // 0..15
    const int bcol = (tid & 15) * 4;  // 0..60

    float acc[4][4] = {};

    for (int k0 = 0; k0 < DM; k0 += 16) {
        float4 a = *(const float4*)&x[(row0 + arow) * DM + k0 + acol];
        As[acol + 0][arow] = a.x;
        As[acol + 1][arow] = a.y;
        As[acol + 2][arow] = a.z;
        As[acol + 3][arow] = a.w;
        *(float4*)&Bs[brow][bcol] =
            *(const float4*)&W[(k0 + brow) * DM + col0 + bcol];
        __syncthreads();

        #pragma unroll
        for (int k = 0; k < 16; k++) {
            float4 av = *(float4*)&As[k][ty * 4];
            float4 bv4 = *(float4*)&Bs[k][tx * 4];
            float ar[4] = {av.x, av.y, av.z, av.w};
            float br[4] = {bv4.x, bv4.y, bv4.z, bv4.w};
            #pragma unroll
            for (int i = 0; i < 4; i++)
                #pragma unroll
                for (int j = 0; j < 4; j++)
                    acc[i][j] = fmaf(ar[i], br[j], acc[i][j]);
        }
        __syncthreads();
    }

    #pragma unroll
    for (int i = 0; i < 4; i++) {
        const int r = row0 + ty * 4 + i;
        const int c = col0 + tx * 4;
        float4 o;
        o.x = acc[i][0] + bias[c + 0];
        o.y = acc[i][1] + bias[c + 1];
        o.z = acc[i][2] + bias[c + 2];
        o.w = acc[i][3] + bias[c + 3];
        *(float4*)&out[r * DM + c] = o;
    }
}

// ---------------------------------------------------------------------------
// Attention: one thread per query row, flash-style online softmax.
// grid = (SEQ/ROWS, NHEAD, BATCH), block = ROWS threads.
// ---------------------------------------------------------------------------
__global__ __launch_bounds__(ROWS) void attn_kernel(float* __restrict__ out)
{
    const int b = blockIdx.z;
    const int h = blockIdx.y;
    const int q0 = blockIdx.x * ROWS;
    const int tid = threadIdx.x;

    __shared__ __align__(16) float Ks[TK][HDIM];
    __shared__ __align__(16) float Vs[TK][HDIM];

    const float scale = 0.125f;  // 1/sqrt(64)
    const int qrow = b * SEQ + q0 + tid;

    // Pre-scaled Q row in registers
    float q[HDIM];
    {
        const float4* qp = (const float4*)&g_q[(size_t)qrow * DM + h * HDIM];
        #pragma unroll
        for (int i = 0; i < HDIM / 4; i++) {
            float4 v = qp[i];
            q[4*i+0] = v.x * scale;
            q[4*i+1] = v.y * scale;
            q[4*i+2] = v.z * scale;
            q[4*i+3] = v.w * scale;
        }
    }

    float m = -1e30f, l = 0.f;
    float o[HDIM] = {};

    for (int kb = 0; kb < SEQ; kb += TK) {
        __syncthreads();
        // Load K/V tiles (64 rows x 64 dims), 8 float4 per thread per tile
        #pragma unroll
        for (int i = 0; i < 8; i++) {
            int idx = i * ROWS + tid;        // 0..1023
            int kr = idx >> 4;               // 0..63
            int dg = (idx & 15) * 4;         // 0..60
            size_t goff = (size_t)(b * SEQ + kb + kr) * DM + h * HDIM + dg;
            *(float4*)&Ks[kr][dg] = *(const float4*)&g_k[goff];
            *(float4*)&Vs[kr][dg] = *(const float4*)&g_v[goff];
        }
        __syncthreads();

        for (int j = 0; j < TK; j++) {
            // s = q . K[j]   (4 independent accumulator chains for ILP)
            float s0 = 0.f, s1 = 0.f, s2 = 0.f, s3 = 0.f;
            #pragma unroll
            for (int d = 0; d < HDIM; d += 4) {
                float4 kv = *(float4*)&Ks[j][d];
                s0 = fmaf(q[d + 0], kv.x, s0);
                s1 = fmaf(q[d + 1], kv.y, s1);
                s2 = fmaf(q[d + 2], kv.z, s2);
                s3 = fmaf(q[d + 3], kv.w, s3);
            }
            float s = (s0 + s1) + (s2 + s3);

            if (s > m) {                      // rare: ~ln(SEQ) times per row
                float alpha = __expf(m - s);
                l *= alpha;
                #pragma unroll
                for (int d = 0; d < HDIM; d++) o[d] *= alpha;
                m = s;
            }
            float p = __expf(s - m);
            l += p;
            #pragma unroll
            for (int d = 0; d < HDIM; d += 4) {
                float4 vv = *(float4*)&Vs[j][d];
                o[d + 0] = fmaf(p, vv.x, o[d + 0]);
                o[d + 1] = fmaf(p, vv.y, o[d + 1]);
                o[d + 2] = fmaf(p, vv.z, o[d + 2]);
                o[d + 3] = fmaf(p, vv.w, o[d + 3]);
            }
        }
    }

    const float inv_l = 1.f / l;
    float* op = &out[(size_t)qrow * DM + h * HDIM];
    #pragma unroll
    for (int d = 0; d < HDIM; d += 4) {
        float4 v;
        v.x = o[d + 0] * inv_l;
        v.y = o[d + 1] * inv_l;
        v.z = o[d + 2] * inv_l;
        v.w = o[d + 3] * inv_l;
        *(float4*)&op[d] = v;
    }
}

// ---------------------------------------------------------------------------
extern "C" void kernel_launch(void* const* d_in, const int* in_sizes, int n_in,
                              void* d_out, int out_size)
{
    const float* x  = (const float*)d_in[0];
    const float* wq = (const float*)d_in[1];
    const float* bq = (const float*)d_in[2];
    const float* wk = (const float*)d_in[3];
    const float* bk = (const float*)d_in[4];
    const float* wv = (const float*)d_in[5];
    const float* bv = (const float*)d_in[6];
    float* out = (float*)d_out;

    dim3 gGemm(DM / 64, MTOT / 64, 3);
    qkv_gemm<<<gGemm, 256>>>(x, wq, bq, wk, bk, wv, bv);

    dim3 gAttn(SEQ / ROWS, NHEAD, BATCH);
    attn_kernel<<<gAttn, ROWS>>>(out);
}